// round 13
// baseline (speedup 1.0000x reference)
#include <cuda_runtime.h>
#include <cuda_fp16.h>
#include <math.h>
#include <cstdint>
#include <stdint.h>

// ---------------- Problem constants ----------------
constexpr int B_    = 16;
constexpr int N_    = 4096;
constexpr int LD    = 256;
constexpr int H_    = 8;
constexpr int DH    = 64;
constexpr int WW    = 128;
constexpr int INNER = 512;   // H_*DH
constexpr int DEPTH = 4;
constexpr int FF    = 1024;
constexpr int SLACK = 50;
constexpr int R_    = B_ * N_;          // 65536 rows
constexpr int QKVW  = 3 * INNER;        // 1536

// ---------------- Scratch ----------------
__device__ float  g_h[(size_t)R_ * LD];          // fp32 residual stream
__device__ __half g_yh[(size_t)R_ * LD];         // LN output (GEMM A)
__device__ __half g_qkvh[(size_t)R_ * QKVW];     // qkv fp16
__device__ __half g_oh[(size_t)R_ * INNER];      // attention out fp16
__device__ __half g_ffh[(size_t)R_ * FF];        // FF hidden fp16
__device__ unsigned g_wp[2097152];               // k-pair-packed fp16 weights
__device__ float  g_cos[(size_t)N_ * 32];
__device__ float  g_sin[(size_t)N_ * 32];
// word offsets into g_wp
constexpr size_t WQKV_OFF = 0;
constexpr size_t WOUT_OFF = 786432;
constexpr size_t W1_OFF   = 1048576;
constexpr size_t W2_OFF   = 1572864;

__device__ __forceinline__ unsigned packh2(float lo, float hi) {
    __half2 h = __floats2half2_rn(lo, hi);
    return *reinterpret_cast<unsigned*>(&h);
}

__device__ __forceinline__ void mma_f16(float* c, unsigned a0, unsigned a1,
                                        unsigned a2, unsigned a3,
                                        unsigned b0, unsigned b1) {
    asm volatile("mma.sync.aligned.m16n8k16.row.col.f32.f16.f16.f32 "
                 "{%0,%1,%2,%3}, {%4,%5,%6,%7}, {%8,%9}, {%0,%1,%2,%3};\n"
                 : "+f"(c[0]), "+f"(c[1]), "+f"(c[2]), "+f"(c[3])
                 : "r"(a0), "r"(a1), "r"(a2), "r"(a3), "r"(b0), "r"(b1));
}

__device__ __forceinline__ unsigned smem_u32(const void* p) {
    return (unsigned)__cvta_generic_to_shared(p);
}
__device__ __forceinline__ void cp16(void* smem, const void* g) {
    unsigned sa = smem_u32(smem);
    asm volatile("cp.async.ca.shared.global [%0], [%1], 16;\n" :: "r"(sa), "l"(g));
}

// ---------------- RoPE table ----------------
__global__ void rope_table_kernel() {
    int idx = blockIdx.x * blockDim.x + threadIdx.x;
    if (idx >= N_ * 32) return;
    int n = idx >> 5, d = idx & 31;
    float invf = (float)(1.0 / pow(10000.0, (double)(2 * d) / 64.0));
    float angf = (float)n * invf;
    double a = (double)angf;
    g_cos[idx] = (float)cos(a);
    g_sin[idx] = (float)sin(a);
}

// ---------------- fused weight packing for all 4 matrices ----------------
__global__ void pack_all_kernel(const float* __restrict__ Wqkv, const float* __restrict__ Wout,
                                const float* __restrict__ W1,  const float* __restrict__ W2) {
    int idx = blockIdx.x * blockDim.x + threadIdx.x;
    if (idx >= 2097152) return;
    const float* src;
    int rel, N;
    size_t off;
    if (idx < 786432)        { src = Wqkv; rel = idx;           N = QKVW; off = WQKV_OFF; }
    else if (idx < 1048576)  { src = Wout; rel = idx - 786432;  N = LD;   off = WOUT_OFF; }
    else if (idx < 1572864)  { src = W1;   rel = idx - 1048576; N = FF;   off = W1_OFF; }
    else                     { src = W2;   rel = idx - 1572864; N = LD;   off = W2_OFF; }
    int kp = rel / N, n = rel - kp * N;
    g_wp[off + rel] = packh2(src[(size_t)(2 * kp) * N + n], src[(size_t)(2 * kp + 1) * N + n]);
}

// ---------------- Expand ----------------
__global__ void expand_kernel(const float* __restrict__ x, const float* __restrict__ We,
                              const float* __restrict__ be, const float* __restrict__ pe) {
    int row = blockIdx.x;
    int c   = threadIdx.x;
    int n   = row & (N_ - 1);
    float x0 = x[row * 2 + 0], x1 = x[row * 2 + 1];
    g_h[(size_t)row * LD + c] = x0 * We[c] + x1 * We[LD + c] + be[c] + pe[n * LD + c];
}

// ---------------- LayerNorm: warp-per-row ----------------
__global__ void ln_kernel(const float* __restrict__ src, __half* __restrict__ dst,
                          const float* __restrict__ gg, const float* __restrict__ bb) {
    int warp = threadIdx.x >> 5, lane = threadIdx.x & 31;
    int row = blockIdx.x * 8 + warp;
    const float* sp = src + (size_t)row * LD + lane * 8;
    float4 v0 = *(const float4*)sp;
    float4 v1 = *(const float4*)(sp + 4);
    float vv[8] = {v0.x, v0.y, v0.z, v0.w, v1.x, v1.y, v1.z, v1.w};
    float s = 0.f, sq = 0.f;
    #pragma unroll
    for (int j = 0; j < 8; j++) { s += vv[j]; sq += vv[j] * vv[j]; }
    #pragma unroll
    for (int o = 16; o > 0; o >>= 1) {
        s  += __shfl_xor_sync(0xffffffffu, s, o);
        sq += __shfl_xor_sync(0xffffffffu, sq, o);
    }
    float mean = s * (1.f / LD);
    float rstd = rsqrtf(sq * (1.f / LD) - mean * mean + 1e-5f);
    const float* gp = gg + lane * 8;
    const float* bp = bb + lane * 8;
    unsigned ow[4];
    #pragma unroll
    for (int j = 0; j < 4; j++) {
        float a = (vv[2 * j]     - mean) * rstd * gp[2 * j]     + bp[2 * j];
        float b = (vv[2 * j + 1] - mean) * rstd * gp[2 * j + 1] + bp[2 * j + 1];
        ow[j] = packh2(a, b);
    }
    *(uint4*)(dst + (size_t)row * LD + lane * 8) = make_uint4(ow[0], ow[1], ow[2], ow[3]);
}

// ---------------- fp16 GEMM: BK=64, m16n8k16, 3-stage cp.async ----------------
constexpr int AST = 36;    // words per A smem row (32 + 4 pad)
constexpr int BST = 132;   // words per B smem row (128 + 4 pad)
constexpr int HG_STAGES = 3;
constexpr int AS_W = 128 * AST;   // 4608 words/stage
constexpr int BS_W = 32 * BST;    // 4224 words/stage
constexpr int HG_SMEM = HG_STAGES * (AS_W + BS_W) * 4;   // 105984 B

template <int EPI>
__global__ __launch_bounds__(256, 2)
void hgemm(const __half* __restrict__ A, const unsigned* __restrict__ Bp,
           void* __restrict__ Cv, const float* __restrict__ bias, int Nc, int K) {
    extern __shared__ unsigned smw[];
    unsigned* AsBase = smw;
    unsigned* BsBase = smw + HG_STAGES * AS_W;

    int tid  = threadIdx.x;
    int row0 = blockIdx.y * 128;
    int col0 = blockIdx.x * 128;
    int lane = tid & 31, w = tid >> 5;
    int gid  = lane >> 2, tig = lane & 3;
    int wr   = w & 1;
    int wc   = w >> 1;

    int ar = tid >> 1;        // 0..127 A row
    int ac = tid & 1;         // chunk parity
    int bk = tid >> 5;        // 0..7 B kp-row (+8, +16, +24)
    int bc = tid & 31;        // 4-word group

    const __half* ApS = A + (size_t)(row0 + ar) * K;
    const unsigned* BpS = Bp + (size_t)bk * Nc + col0 + bc * 4;

    float acc[4][4][4];
    #pragma unroll
    for (int mi = 0; mi < 4; mi++)
        #pragma unroll
        for (int ni = 0; ni < 4; ni++)
            #pragma unroll
            for (int e = 0; e < 4; e++) acc[mi][ni][e] = 0.f;

    int NT = K >> 6;   // k=64 per tile (min NT = 4 here)

    auto stage = [&](int kti, int buf) {
        unsigned* Asb = AsBase + buf * AS_W;
        unsigned* Bsb = BsBase + buf * BS_W;
        const __half* as = ApS + kti * 64 + ac * 8;
        cp16(&Asb[ar * AST + ac * 4], as);
        cp16(&Asb[ar * AST + ac * 4 + 8], as + 16);
        cp16(&Asb[ar * AST + ac * 4 + 16], as + 32);
        cp16(&Asb[ar * AST + ac * 4 + 24], as + 48);
        const unsigned* bs = BpS + (size_t)kti * 32 * Nc;
        cp16(&Bsb[bk * BST + bc * 4], bs);
        cp16(&Bsb[(bk + 8) * BST + bc * 4], bs + (size_t)8 * Nc);
        cp16(&Bsb[(bk + 16) * BST + bc * 4], bs + (size_t)16 * Nc);
        cp16(&Bsb[(bk + 24) * BST + bc * 4], bs + (size_t)24 * Nc);
    };

    stage(0, 0);
    asm volatile("cp.async.commit_group;\n");
    stage(1, 1);
    asm volatile("cp.async.commit_group;\n");

    for (int it = 0; it < NT; it++) {
        int cur = it % HG_STAGES;
        asm volatile("cp.async.wait_group 1;\n");
        __syncthreads();
        if (it + 2 < NT) stage(it + 2, (it + 2) % HG_STAGES);
        asm volatile("cp.async.commit_group;\n");

        const unsigned* Asb = AsBase + cur * AS_W;
        const unsigned* Bsb = BsBase + cur * BS_W;

        #pragma unroll
        for (int s = 0; s < 4; s++) {
            uint2 fA[4][2];
            #pragma unroll
            for (int mi = 0; mi < 4; mi++) {
                int m = wr * 64 + mi * 16 + gid;
                fA[mi][0] = *(const uint2*)&Asb[m * AST + s * 8 + 2 * tig];
                fA[mi][1] = *(const uint2*)&Asb[(m + 8) * AST + s * 8 + 2 * tig];
            }
            #pragma unroll
            for (int ni = 0; ni < 4; ni++) {
                int n = wc * 32 + ni * 8 + gid;
                unsigned b0 = Bsb[(s * 8 + 2 * tig) * BST + n];
                unsigned b1 = Bsb[(s * 8 + 2 * tig + 1) * BST + n];
                #pragma unroll
                for (int mi = 0; mi < 4; mi++) {
                    mma_f16(acc[mi][ni], fA[mi][0].x, fA[mi][1].x,
                            fA[mi][0].y, fA[mi][1].y, b0, b1);
                }
            }
        }
    }

    __half* Ch = (__half*)Cv;
    float*  Cf = (float*)Cv;
    #pragma unroll
    for (int mi = 0; mi < 4; mi++) {
        int ra = row0 + wr * 64 + mi * 16 + gid;
        #pragma unroll
        for (int ni = 0; ni < 4; ni++) {
            int cc = col0 + wc * 32 + ni * 8 + tig * 2;
            #pragma unroll
            for (int half = 0; half < 2; half++) {
                int r = ra + half * 8;
                float v0 = acc[mi][ni][half * 2 + 0];
                float v1 = acc[mi][ni][half * 2 + 1];
                size_t off = (size_t)r * Nc + cc;
                if (EPI == 0) {
                    *(__half2*)&Ch[off] = __floats2half2_rn(v0, v1);
                } else if (EPI == 1) {
                    v0 += bias[cc];
                    v1 += bias[cc + 1];
                    v0 = 0.5f * v0 * (1.f + erff(v0 * 0.70710678118654752f));
                    v1 = 0.5f * v1 * (1.f + erff(v1 * 0.70710678118654752f));
                    *(__half2*)&Ch[off] = __floats2half2_rn(v0, v1);
                } else if (EPI == 2) {
                    float2 c = *(float2*)&Cf[off];
                    c.x += v0; c.y += v1;
                    *(float2*)&Cf[off] = c;
                } else {
                    float2 c = *(float2*)&Cf[off];
                    c.x += v0 + bias[cc]; c.y += v1 + bias[cc + 1];
                    *(float2*)&Cf[off] = c;
                }
            }
        }
    }
}

// ---------------- fp16 tensor-core flash local attention (no online max) ----------------
constexpr int KST = 260;
constexpr int QST = 34;
constexpr int VST = 68;
constexpr int PST = 36;
constexpr int KS_OFF = 0;
constexpr int QS_OFF = 32 * KST;
constexpr int VS_OFF = QS_OFF + 128 * QST;
constexpr int PS_OFF = VS_OFF + 128 * VST;
constexpr int ATTN_SMEM = (PS_OFF + 8 * 16 * PST) * 4;

__global__ __launch_bounds__(256)
void attn_mma_kernel(const __half* __restrict__ qkv, __half* __restrict__ outp) {
    extern __shared__ unsigned smU[];

    int w = blockIdx.x, head = blockIdx.y, b = blockIdx.z;
    int tid  = threadIdx.x;
    int lane = tid & 31;
    int wm   = tid >> 5;
    int gid  = lane >> 2, tig = lane & 3;
    int qbase = w * WW;
    size_t rowbase = (size_t)b * N_;

    {
        int jj = tid;
        int p = qbase - WW + jj;
        float kv[64];
        if (p >= 0) {
            const __half2* kp2 = (const __half2*)(qkv + (rowbase + p) * QKVW + INNER + head * DH);
            float raw[64];
            #pragma unroll
            for (int i = 0; i < 32; i++) {
                float2 f = __half22float2(kp2[i]);
                raw[2 * i] = f.x; raw[2 * i + 1] = f.y;
            }
            #pragma unroll
            for (int d = 0; d < 32; d++) {
                float cs = g_cos[p * 32 + d], sn = g_sin[p * 32 + d];
                kv[d]      = raw[d] * cs - raw[d + 32] * sn;
                kv[d + 32] = raw[d + 32] * cs + raw[d] * sn;
            }
        } else {
            #pragma unroll
            for (int d = 0; d < 64; d++) kv[d] = 0.f;
        }
        #pragma unroll
        for (int dp = 0; dp < 32; dp++)
            smU[KS_OFF + dp * KST + jj] = packh2(kv[2 * dp], kv[2 * dp + 1]);
    }
    {
        int jp = tid >> 1;
        int dh = (tid & 1) * 32;
        int p0 = qbase - WW + 2 * jp;
        unsigned* vrow = smU + VS_OFF + jp * VST + dh;
        if (p0 >= 0) {
            const __half2* vA = (const __half2*)(qkv + (rowbase + p0) * QKVW + 2 * INNER + head * DH + dh);
            const __half2* vB = (const __half2*)(qkv + (rowbase + p0 + 1) * QKVW + 2 * INNER + head * DH + dh);
            #pragma unroll
            for (int i = 0; i < 16; i++) {
                float2 fa = __half22float2(vA[i]);
                float2 fb = __half22float2(vB[i]);
                vrow[2 * i]     = packh2(fa.x, fb.x);
                vrow[2 * i + 1] = packh2(fa.y, fb.y);
            }
        } else {
            #pragma unroll
            for (int i = 0; i < 32; i++) vrow[i] = 0u;
        }
    }
    if (tid < 128) {
        int r = tid;
        int i = qbase + r;
        const __half2* qp2 = (const __half2*)(qkv + (rowbase + i) * QKVW + head * DH);
        float raw[64], qv[64];
        #pragma unroll
        for (int ii = 0; ii < 32; ii++) {
            float2 f = __half22float2(qp2[ii]);
            raw[2 * ii] = f.x; raw[2 * ii + 1] = f.y;
        }
        #pragma unroll
        for (int d = 0; d < 32; d++) {
            float cs = g_cos[i * 32 + d], sn = g_sin[i * 32 + d];
            qv[d]      = (raw[d] * cs - raw[d + 32] * sn) * 0.125f;
            qv[d + 32] = (raw[d + 32] * cs + raw[d] * sn) * 0.125f;
        }
        #pragma unroll
        for (int j = 0; j < 32; j++)
            smU[QS_OFF + r * QST + j] = packh2(qv[2 * j], qv[2 * j + 1]);
    }
    __syncthreads();

    unsigned qa[4][4];
    {
        int rA = wm * 16 + gid, rB = rA + 8;
        #pragma unroll
        for (int s = 0; s < 4; s++) {
            uint2 u0 = *(const uint2*)&smU[QS_OFF + rA * QST + s * 8 + 2 * tig];
            uint2 u1 = *(const uint2*)&smU[QS_OFF + rB * QST + s * 8 + 2 * tig];
            qa[s][0] = u0.x; qa[s][1] = u1.x; qa[s][2] = u0.y; qa[s][3] = u1.y;
        }
    }

    float O[8][4];
    #pragma unroll
    for (int nf = 0; nf < 8; nf++)
        #pragma unroll
        for (int e = 0; e < 4; e++) O[nf][e] = 0.f;
    float l0 = 0.f, l1 = 0.f;

    unsigned* Ps = smU + PS_OFF + wm * 16 * PST;
    int Imin = qbase + wm * 16;
    int Imax = Imin + 15;
    int i0 = Imin + gid;
    int i1 = i0 + 8;

    int clo = wm >> 2, chi = clo + 2;
    if (w == 0) clo = 2;

    for (int c = clo; c <= chi; c++) {
        int jbase = qbase - WW + c * 64;
        float S[8][4];
        #pragma unroll
        for (int nf = 0; nf < 8; nf++)
            #pragma unroll
            for (int e = 0; e < 4; e++) S[nf][e] = 0.f;
        #pragma unroll
        for (int nf = 0; nf < 8; nf++) {
            int jlo = jbase + nf * 8;
            if (jlo > Imax || jlo + 7 < Imin - WW) continue;
            int n = c * 64 + nf * 8 + gid;
            #pragma unroll
            for (int s = 0; s < 4; s++) {
                unsigned b0 = smU[KS_OFF + (s * 8 + 2 * tig) * KST + n];
                unsigned b1 = smU[KS_OFF + (s * 8 + 2 * tig + 1) * KST + n];
                mma_f16(S[nf], qa[s][0], qa[s][1], qa[s][2], qa[s][3], b0, b1);
            }
        }
        #pragma unroll
        for (int nf = 0; nf < 8; nf++) {
            int j0 = jbase + nf * 8 + 2 * tig;
            if (i0 < j0     || i0 - j0 > WW)     S[nf][0] = -1e9f;
            if (i0 < j0 + 1 || i0 - j0 - 1 > WW) S[nf][1] = -1e9f;
            if (i1 < j0     || i1 - j0 > WW)     S[nf][2] = -1e9f;
            if (i1 < j0 + 1 || i1 - j0 - 1 > WW) S[nf][3] = -1e9f;
        }
        float ls0 = 0.f, ls1 = 0.f;
        #pragma unroll
        for (int nf = 0; nf < 8; nf++) {
            float p0 = __expf(S[nf][0]);
            float p1 = __expf(S[nf][1]);
            float p2 = __expf(S[nf][2]);
            float p3 = __expf(S[nf][3]);
            ls0 += p0 + p1;
            ls1 += p2 + p3;
            int jp = nf * 4 + tig;
            Ps[gid * PST + jp]       = packh2(p0, p1);
            Ps[(gid + 8) * PST + jp] = packh2(p2, p3);
        }
        l0 += ls0;
        l1 += ls1;
        __syncwarp();
        unsigned pa[4][4];
        #pragma unroll
        for (int s = 0; s < 4; s++) {
            uint2 u0 = *(const uint2*)&Ps[gid * PST + s * 8 + 2 * tig];
            uint2 u1 = *(const uint2*)&Ps[(gid + 8) * PST + s * 8 + 2 * tig];
            pa[s][0] = u0.x; pa[s][1] = u1.x; pa[s][2] = u0.y; pa[s][3] = u1.y;
        }
        #pragma unroll
        for (int nd = 0; nd < 8; nd++) {
            int n = nd * 8 + gid;
            #pragma unroll
            for (int s = 0; s < 4; s++) {
                int jbl = jbase + s * 16;
                if (jbl > Imax || jbl + 15 < Imin - WW) continue;
                unsigned b0 = smU[VS_OFF + (c * 32 + s * 8 + 2 * tig) * VST + n];
                unsigned b1 = smU[VS_OFF + (c * 32 + s * 8 + 2 * tig + 1) * VST + n];
                mma_f16(O[nd], pa[s][0], pa[s][1], pa[s][2], pa[s][3], b0, b1);
            }
        }
        __syncwarp();
    }

    l0 += __shfl_xor_sync(0xffffffffu, l0, 1);
    l0 += __shfl_xor_sync(0xffffffffu, l0, 2);
    l1 += __shfl_xor_sync(0xffffffffu, l1, 1);
    l1 += __shfl_xor_sync(0xffffffffu, l1, 2);
    float inv0 = 1.f / l0, inv1 = 1.f / l1;

    __half* op0 = outp + (rowbase + i0) * INNER + head * DH;
    __half* op1 = outp + (rowbase + i1) * INNER + head * DH;
    #pragma unroll
    for (int nd = 0; nd < 8; nd++) {
        int d0 = nd * 8 + 2 * tig;
        *(__half2*)&op0[d0] = __floats2half2_rn(O[nd][0] * inv0, O[nd][1] * inv0);
        *(__half2*)&op1[d0] = __floats2half2_rn(O[nd][2] * inv1, O[nd][3] * inv1);
    }
}

// ---------------- Final LN + logits + slice: warp-per-row ----------------
__global__ void final_kernel(const float* __restrict__ gg, const float* __restrict__ bb,
                             const float* __restrict__ wl, float* __restrict__ out) {
    int warp = threadIdx.x >> 5, lane = threadIdx.x & 31;
    int row = blockIdx.x * 8 + warp;
    int n = row & (N_ - 1);
    if (n < SLACK || n >= N_ - SLACK) return;   // warp-uniform
    const float* sp = g_h + (size_t)row * LD + lane * 8;
    float4 v0 = *(const float4*)sp;
    float4 v1 = *(const float4*)(sp + 4);
    float vv[8] = {v0.x, v0.y, v0.z, v0.w, v1.x, v1.y, v1.z, v1.w};
    float s = 0.f, sq = 0.f;
    #pragma unroll
    for (int j = 0; j < 8; j++) { s += vv[j]; sq += vv[j] * vv[j]; }
    #pragma unroll
    for (int o = 16; o > 0; o >>= 1) {
        s  += __shfl_xor_sync(0xffffffffu, s, o);
        sq += __shfl_xor_sync(0xffffffffu, sq, o);
    }
    float mean = s * (1.f / LD);
    float rstd = rsqrtf(sq * (1.f / LD) - mean * mean + 1e-5f);
    const float* gp = gg + lane * 8;
    const float* bp = bb + lane * 8;
    const float* wp = wl + lane * 8;
    float contrib = 0.f;
    #pragma unroll
    for (int j = 0; j < 8; j++)
        contrib += ((vv[j] - mean) * rstd * gp[j] + bp[j]) * wp[j];
    #pragma unroll
    for (int o = 16; o > 0; o >>= 1)
        contrib += __shfl_xor_sync(0xffffffffu, contrib, o);
    if (lane == 0) {
        int bidx = row >> 12;
        out[bidx * (N_ - 2 * SLACK) + (n - SLACK)] = contrib;
    }
}

// ---------------- Launch ----------------
extern "C" void kernel_launch(void* const* d_in, const int* in_sizes, int n_in,
                              void* d_out, int out_size) {
    const float* x        = (const float*)d_in[0];
    const float* W_exp    = (const float*)d_in[1];
    const float* b_exp    = (const float*)d_in[2];
    const float* pos_emb  = (const float*)d_in[3];
    const float* ln_att_g = (const float*)d_in[4];
    const float* ln_att_b = (const float*)d_in[5];
    const float* Wqkv     = (const float*)d_in[6];
    const float* Wout     = (const float*)d_in[7];
    const float* ln_ff_g  = (const float*)d_in[8];
    const float* ln_ff_b  = (const float*)d_in[9];
    const float* W1       = (const float*)d_in[10];
    const float* b1       = (const float*)d_in[11];
    const float* W2       = (const float*)d_in[12];
    const float* b2       = (const float*)d_in[13];
    const float* ln_f_g   = (const float*)d_in[14];
    const float* ln_f_b   = (const float*)d_in[15];
    const float* W_logits = (const float*)d_in[16];
    float* out = (float*)d_out;

    float *ph;
    __half *pyh, *pqkvh, *poh, *pffh;
    unsigned *pwp;
    cudaGetSymbolAddress((void**)&ph,    g_h);
    cudaGetSymbolAddress((void**)&pyh,   g_yh);
    cudaGetSymbolAddress((void**)&pqkvh, g_qkvh);
    cudaGetSymbolAddress((void**)&poh,   g_oh);
    cudaGetSymbolAddress((void**)&pffh,  g_ffh);
    cudaGetSymbolAddress((void**)&pwp,   g_wp);

    cudaFuncSetAttribute(attn_mma_kernel, cudaFuncAttributeMaxDynamicSharedMemorySize, ATTN_SMEM);
    cudaFuncSetAttribute(hgemm<0>, cudaFuncAttributeMaxDynamicSharedMemorySize, HG_SMEM);
    cudaFuncSetAttribute(hgemm<1>, cudaFuncAttributeMaxDynamicSharedMemorySize, HG_SMEM);
    cudaFuncSetAttribute(hgemm<2>, cudaFuncAttributeMaxDynamicSharedMemorySize, HG_SMEM);
    cudaFuncSetAttribute(hgemm<3>, cudaFuncAttributeMaxDynamicSharedMemorySize, HG_SMEM);

    // launch order keeps attn_mma_kernel at launch index 5 for the ncu capture window
    rope_table_kernel<<<(N_ * 32 + 255) / 256, 256>>>();                       // 0
    pack_all_kernel<<<(2097152 + 255) / 256, 256>>>(Wqkv, Wout, W1, W2);       // 1
    expand_kernel<<<R_, LD>>>(x, W_exp, b_exp, pos_emb);                       // 2

    for (int l = 0; l < DEPTH; ++l) {
        ln_kernel<<<R_ / 8, 256>>>(ph, pyh, ln_att_g + l * LD, ln_att_b + l * LD);  // 3
        hgemm<0><<<dim3(QKVW / 128, R_ / 128), 256, HG_SMEM>>>(
            pyh, pwp + WQKV_OFF + (size_t)l * (LD / 2) * QKVW, pqkvh, nullptr, QKVW, LD);  // 4
        attn_mma_kernel<<<dim3(N_ / WW, H_, B_), 256, ATTN_SMEM>>>(pqkvh, poh);            // 5
        hgemm<2><<<dim3(LD / 128, R_ / 128), 256, HG_SMEM>>>(
            poh, pwp + WOUT_OFF + (size_t)l * (INNER / 2) * LD, ph, nullptr, LD, INNER);
        ln_kernel<<<R_ / 8, 256>>>(ph, pyh, ln_ff_g + l * LD, ln_ff_b + l * LD);
        hgemm<1><<<dim3(FF / 128, R_ / 128), 256, HG_SMEM>>>(
            pyh, pwp + W1_OFF + (size_t)l * (LD / 2) * FF, pffh, b1 + (size_t)l * FF, FF, LD);
        hgemm<3><<<dim3(LD / 128, R_ / 128), 256, HG_SMEM>>>(
            pffh, pwp + W2_OFF + (size_t)l * (FF / 2) * LD, ph, b2 + (size_t)l * LD, LD, FF);
    }

    final_kernel<<<R_ / 8, 256>>>(ln_f_g, ln_f_b, W_logits, out);
}

// round 14
// speedup vs baseline: 1.0733x; 1.0733x over previous
#include <cuda_runtime.h>
#include <cuda_fp16.h>
#include <math.h>

// ---------------- Problem constants ----------------
constexpr int B_    = 16;
constexpr int N_    = 4096;
constexpr int LD    = 256;
constexpr int H_    = 8;
constexpr int DH    = 64;
constexpr int WW    = 128;
constexpr int INNER = 512;   // H_*DH
constexpr int DEPTH = 4;
constexpr int FF    = 1024;
constexpr int SLACK = 50;
constexpr int R_    = B_ * N_;          // 65536 rows
constexpr int QKVW  = 3 * INNER;        // 1536

// ---------------- Scratch ----------------
__device__ float  g_h[(size_t)R_ * LD];          // fp32 residual stream
__device__ __half g_yh[(size_t)R_ * LD];         // LN output (GEMM A)
__device__ __half g_qkvh[(size_t)R_ * QKVW];     // qkv fp16
__device__ __half g_oh[(size_t)R_ * INNER];      // attention out fp16
__device__ __half g_ffh[(size_t)R_ * FF];        // FF hidden fp16
__device__ unsigned g_wp[2097152];               // k-pair-packed fp16 weights
__device__ float  g_cos[(size_t)N_ * 32];
__device__ float  g_sin[(size_t)N_ * 32];
// word offsets into g_wp
constexpr size_t WQKV_OFF = 0;
constexpr size_t WOUT_OFF = 786432;
constexpr size_t W1_OFF   = 1048576;
constexpr size_t W2_OFF   = 1572864;

__device__ __forceinline__ unsigned packh2(float lo, float hi) {
    __half2 h = __floats2half2_rn(lo, hi);
    return *reinterpret_cast<unsigned*>(&h);
}

__device__ __forceinline__ void mma_f16(float* c, unsigned a0, unsigned a1,
                                        unsigned a2, unsigned a3,
                                        unsigned b0, unsigned b1) {
    asm volatile("mma.sync.aligned.m16n8k16.row.col.f32.f16.f16.f32 "
                 "{%0,%1,%2,%3}, {%4,%5,%6,%7}, {%8,%9}, {%0,%1,%2,%3};\n"
                 : "+f"(c[0]), "+f"(c[1]), "+f"(c[2]), "+f"(c[3])
                 : "r"(a0), "r"(a1), "r"(a2), "r"(a3), "r"(b0), "r"(b1));
}

__device__ __forceinline__ void cp16(void* smem, const void* g) {
    unsigned sa = (unsigned)__cvta_generic_to_shared(smem);
    asm volatile("cp.async.ca.shared.global [%0], [%1], 16;\n" :: "r"(sa), "l"(g));
}

// ---------------- RoPE table ----------------
__global__ void rope_table_kernel() {
    int idx = blockIdx.x * blockDim.x + threadIdx.x;
    if (idx >= N_ * 32) return;
    int n = idx >> 5, d = idx & 31;
    float invf = (float)(1.0 / pow(10000.0, (double)(2 * d) / 64.0));
    float angf = (float)n * invf;
    double a = (double)angf;
    g_cos[idx] = (float)cos(a);
    g_sin[idx] = (float)sin(a);
}

// ---------------- weight packing: W[K][N] fp32 -> out[K/2][N] half2-words ----------------
__global__ void pack_w_kernel(const float* __restrict__ W, unsigned* __restrict__ out,
                              int rows2, int N) {
    int idx = blockIdx.x * blockDim.x + threadIdx.x;
    if (idx >= rows2 * N) return;
    int kp = idx / N, n = idx - kp * N;
    out[idx] = packh2(W[(size_t)(2 * kp) * N + n], W[(size_t)(2 * kp + 1) * N + n]);
}

// ---------------- Expand ----------------
__global__ void expand_kernel(const float* __restrict__ x, const float* __restrict__ We,
                              const float* __restrict__ be, const float* __restrict__ pe) {
    int row = blockIdx.x;
    int c   = threadIdx.x;
    int n   = row & (N_ - 1);
    float x0 = x[row * 2 + 0], x1 = x[row * 2 + 1];
    g_h[(size_t)row * LD + c] = x0 * We[c] + x1 * We[LD + c] + be[c] + pe[n * LD + c];
}

// ---------------- LayerNorm (fp32 in, fp16 out) ----------------
__global__ void ln_kernel(const float* __restrict__ src, __half* __restrict__ dst,
                          const float* __restrict__ gg, const float* __restrict__ bb) {
    int row = blockIdx.x, c = threadIdx.x;
    float v = src[(size_t)row * LD + c];
    float s = v, sq = v * v;
    #pragma unroll
    for (int o = 16; o > 0; o >>= 1) {
        s  += __shfl_down_sync(0xffffffffu, s, o);
        sq += __shfl_down_sync(0xffffffffu, sq, o);
    }
    __shared__ float sh[16];
    __shared__ float stat[2];
    if ((c & 31) == 0) { sh[c >> 5] = s; sh[8 + (c >> 5)] = sq; }
    __syncthreads();
    if (c == 0) {
        float S = 0.f, SQ = 0.f;
        #pragma unroll
        for (int i = 0; i < 8; i++) { S += sh[i]; SQ += sh[8 + i]; }
        float mean = S * (1.f / LD);
        stat[0] = mean;
        stat[1] = rsqrtf(SQ * (1.f / LD) - mean * mean + 1e-5f);
    }
    __syncthreads();
    dst[(size_t)row * LD + c] = __float2half_rn((v - stat[0]) * stat[1] * gg[c] + bb[c]);
}

// ---------------- fp16 GEMM: BK=32, m16n8k16, 3-stage cp.async ----------------
// A: fp16 k-major [M][K]; B: packed words [K/2][N].
// EPI: 0 = half store, 1 = +bias, GELU, half store, 2 = fp32 C += AB, 3 = fp32 C += AB + bias
constexpr int AST = 20;    // words per A smem row (16 + 4 pad; 80B, 16B-aligned)
constexpr int BST = 132;   // words per B smem row (128 + 4 pad)
constexpr int HG_STAGES = 3;
constexpr int AS_W = 128 * AST;    // words per A stage
constexpr int BS_W = 16 * BST;     // words per B stage
constexpr int HG_SMEM = HG_STAGES * (AS_W + BS_W) * 4;   // 56064 B

template <int EPI>
__global__ __launch_bounds__(256, 2)
void hgemm(const __half* __restrict__ A, const unsigned* __restrict__ Bp,
           void* __restrict__ Cv, const float* __restrict__ bias, int Nc, int K) {
    extern __shared__ unsigned smw[];
    unsigned* AsBase = smw;
    unsigned* BsBase = smw + HG_STAGES * AS_W;

    int tid  = threadIdx.x;
    int row0 = blockIdx.y * 128;
    int col0 = blockIdx.x * 128;
    int lane = tid & 31, w = tid >> 5;
    int gid  = lane >> 2, tig = lane & 3;
    int wr   = w & 1;
    int wc   = w >> 1;

    int ar = tid >> 1;        // 0..127 A row
    int ac = tid & 1;         // chunk parity: chunks {ac, ac+2} of 4 x 16B
    int bk = tid >> 5;        // 0..7 B kp-row (+8 second)
    int bc = tid & 31;        // 4-word group

    const __half* ApS = A + (size_t)(row0 + ar) * K;
    const unsigned* BpS = Bp + (size_t)bk * Nc + col0 + bc * 4;

    float acc[4][4][4];
    #pragma unroll
    for (int mi = 0; mi < 4; mi++)
        #pragma unroll
        for (int ni = 0; ni < 4; ni++)
            #pragma unroll
            for (int e = 0; e < 4; e++) acc[mi][ni][e] = 0.f;

    int NT = K >> 5;   // k=32 per iter

    auto stage = [&](int kti, int buf) {
        unsigned* Asb = AsBase + buf * AS_W;
        unsigned* Bsb = BsBase + buf * BS_W;
        const __half* as = ApS + kti * 32 + ac * 8;
        cp16(&Asb[ar * AST + ac * 4], as);
        cp16(&Asb[ar * AST + ac * 4 + 8], as + 16);
        const unsigned* bs = BpS + (size_t)kti * 16 * Nc;
        cp16(&Bsb[bk * BST + bc * 4], bs);
        cp16(&Bsb[(bk + 8) * BST + bc * 4], bs + (size_t)8 * Nc);
    };

    stage(0, 0);
    asm volatile("cp.async.commit_group;\n");
    stage(1, 1);
    asm volatile("cp.async.commit_group;\n");

    for (int it = 0; it < NT; it++) {
        int cur = it % HG_STAGES;
        asm volatile("cp.async.wait_group 1;\n");
        __syncthreads();
        if (it + 2 < NT) stage(it + 2, (it + 2) % HG_STAGES);
        asm volatile("cp.async.commit_group;\n");

        const unsigned* Asb = AsBase + cur * AS_W;
        const unsigned* Bsb = BsBase + cur * BS_W;

        #pragma unroll
        for (int s = 0; s < 2; s++) {
            uint2 fA[4][2];
            #pragma unroll
            for (int mi = 0; mi < 4; mi++) {
                int m = wr * 64 + mi * 16 + gid;
                fA[mi][0] = *(const uint2*)&Asb[m * AST + s * 8 + 2 * tig];
                fA[mi][1] = *(const uint2*)&Asb[(m + 8) * AST + s * 8 + 2 * tig];
            }
            #pragma unroll
            for (int ni = 0; ni < 4; ni++) {
                int n = wc * 32 + ni * 8 + gid;
                unsigned b0 = Bsb[(s * 8 + 2 * tig) * BST + n];
                unsigned b1 = Bsb[(s * 8 + 2 * tig + 1) * BST + n];
                #pragma unroll
                for (int mi = 0; mi < 4; mi++) {
                    mma_f16(acc[mi][ni], fA[mi][0].x, fA[mi][1].x,
                            fA[mi][0].y, fA[mi][1].y, b0, b1);
                }
            }
        }
    }

    __half* Ch = (__half*)Cv;
    float*  Cf = (float*)Cv;
    #pragma unroll
    for (int mi = 0; mi < 4; mi++) {
        int ra = row0 + wr * 64 + mi * 16 + gid;
        #pragma unroll
        for (int ni = 0; ni < 4; ni++) {
            int cc = col0 + wc * 32 + ni * 8 + tig * 2;
            #pragma unroll
            for (int half = 0; half < 2; half++) {
                int r = ra + half * 8;
                float v0 = acc[mi][ni][half * 2 + 0];
                float v1 = acc[mi][ni][half * 2 + 1];
                size_t off = (size_t)r * Nc + cc;
                if (EPI == 0) {
                    *(__half2*)&Ch[off] = __floats2half2_rn(v0, v1);
                } else if (EPI == 1) {
                    v0 += bias[cc];
                    v1 += bias[cc + 1];
                    v0 = 0.5f * v0 * (1.f + erff(v0 * 0.70710678118654752f));
                    v1 = 0.5f * v1 * (1.f + erff(v1 * 0.70710678118654752f));
                    *(__half2*)&Ch[off] = __floats2half2_rn(v0, v1);
                } else if (EPI == 2) {
                    Cf[off]     += v0;
                    Cf[off + 1] += v1;
                } else {
                    Cf[off]     += v0 + bias[cc];
                    Cf[off + 1] += v1 + bias[cc + 1];
                }
            }
        }
    }
}

// ---------------- fp16 tensor-core flash local attention ----------------
constexpr int KST = 260;
constexpr int QST = 34;
constexpr int VST = 68;
constexpr int PST = 36;
constexpr int KS_OFF = 0;
constexpr int QS_OFF = 32 * KST;
constexpr int VS_OFF = QS_OFF + 128 * QST;
constexpr int PS_OFF = VS_OFF + 128 * VST;
constexpr int ATTN_SMEM = (PS_OFF + 8 * 16 * PST) * 4;

__global__ __launch_bounds__(256)
void attn_mma_kernel(const __half* __restrict__ qkv, __half* __restrict__ outp) {
    extern __shared__ unsigned smU[];

    int w = blockIdx.x, head = blockIdx.y, b = blockIdx.z;
    int tid  = threadIdx.x;
    int lane = tid & 31;
    int wm   = tid >> 5;
    int gid  = lane >> 2, tig = lane & 3;
    int qbase = w * WW;
    size_t rowbase = (size_t)b * N_;

    {
        int jj = tid;
        int p = qbase - WW + jj;
        float kv[64];
        if (p >= 0) {
            const __half2* kp2 = (const __half2*)(qkv + (rowbase + p) * QKVW + INNER + head * DH);
            float raw[64];
            #pragma unroll
            for (int i = 0; i < 32; i++) {
                float2 f = __half22float2(kp2[i]);
                raw[2 * i] = f.x; raw[2 * i + 1] = f.y;
            }
            #pragma unroll
            for (int d = 0; d < 32; d++) {
                float cs = g_cos[p * 32 + d], sn = g_sin[p * 32 + d];
                kv[d]      = raw[d] * cs - raw[d + 32] * sn;
                kv[d + 32] = raw[d + 32] * cs + raw[d] * sn;
            }
        } else {
            #pragma unroll
            for (int d = 0; d < 64; d++) kv[d] = 0.f;
        }
        #pragma unroll
        for (int dp = 0; dp < 32; dp++)
            smU[KS_OFF + dp * KST + jj] = packh2(kv[2 * dp], kv[2 * dp + 1]);
    }
    {
        int jp = tid >> 1;
        int dh = (tid & 1) * 32;
        int p0 = qbase - WW + 2 * jp;
        unsigned* vrow = smU + VS_OFF + jp * VST + dh;
        if (p0 >= 0) {
            const __half2* vA = (const __half2*)(qkv + (rowbase + p0) * QKVW + 2 * INNER + head * DH + dh);
            const __half2* vB = (const __half2*)(qkv + (rowbase + p0 + 1) * QKVW + 2 * INNER + head * DH + dh);
            #pragma unroll
            for (int i = 0; i < 16; i++) {
                float2 fa = __half22float2(vA[i]);
                float2 fb = __half22float2(vB[i]);
                vrow[2 * i]     = packh2(fa.x, fb.x);
                vrow[2 * i + 1] = packh2(fa.y, fb.y);
            }
        } else {
            #pragma unroll
            for (int i = 0; i < 32; i++) vrow[i] = 0u;
        }
    }
    if (tid < 128) {
        int r = tid;
        int i = qbase + r;
        const __half2* qp2 = (const __half2*)(qkv + (rowbase + i) * QKVW + head * DH);
        float raw[64], qv[64];
        #pragma unroll
        for (int ii = 0; ii < 32; ii++) {
            float2 f = __half22float2(qp2[ii]);
            raw[2 * ii] = f.x; raw[2 * ii + 1] = f.y;
        }
        #pragma unroll
        for (int d = 0; d < 32; d++) {
            float cs = g_cos[i * 32 + d], sn = g_sin[i * 32 + d];
            qv[d]      = (raw[d] * cs - raw[d + 32] * sn) * 0.125f;
            qv[d + 32] = (raw[d + 32] * cs + raw[d] * sn) * 0.125f;
        }
        #pragma unroll
        for (int j = 0; j < 32; j++)
            smU[QS_OFF + r * QST + j] = packh2(qv[2 * j], qv[2 * j + 1]);
    }
    __syncthreads();

    unsigned qa[4][4];
    {
        int rA = wm * 16 + gid, rB = rA + 8;
        #pragma unroll
        for (int s = 0; s < 4; s++) {
            uint2 u0 = *(const uint2*)&smU[QS_OFF + rA * QST + s * 8 + 2 * tig];
            uint2 u1 = *(const uint2*)&smU[QS_OFF + rB * QST + s * 8 + 2 * tig];
            qa[s][0] = u0.x; qa[s][1] = u1.x; qa[s][2] = u0.y; qa[s][3] = u1.y;
        }
    }

    float O[8][4];
    #pragma unroll
    for (int nf = 0; nf < 8; nf++)
        #pragma unroll
        for (int e = 0; e < 4; e++) O[nf][e] = 0.f;
    float m0 = -1e30f, m1 = -1e30f, l0 = 0.f, l1 = 0.f;

    unsigned* Ps = smU + PS_OFF + wm * 16 * PST;
    int Imin = qbase + wm * 16;
    int Imax = Imin + 15;
    int i0 = Imin + gid;
    int i1 = i0 + 8;

    int clo = wm >> 2, chi = clo + 2;
    if (w == 0) clo = 2;

    for (int c = clo; c <= chi; c++) {
        int jbase = qbase - WW + c * 64;
        float S[8][4];
        #pragma unroll
        for (int nf = 0; nf < 8; nf++)
            #pragma unroll
            for (int e = 0; e < 4; e++) S[nf][e] = 0.f;
        #pragma unroll
        for (int nf = 0; nf < 8; nf++) {
            int jlo = jbase + nf * 8;
            if (jlo > Imax || jlo + 7 < Imin - WW) continue;
            int n = c * 64 + nf * 8 + gid;
            #pragma unroll
            for (int s = 0; s < 4; s++) {
                unsigned b0 = smU[KS_OFF + (s * 8 + 2 * tig) * KST + n];
                unsigned b1 = smU[KS_OFF + (s * 8 + 2 * tig + 1) * KST + n];
                mma_f16(S[nf], qa[s][0], qa[s][1], qa[s][2], qa[s][3], b0, b1);
            }
        }
        float rmax0 = -1e30f, rmax1 = -1e30f;
        #pragma unroll
        for (int nf = 0; nf < 8; nf++) {
            int j0 = jbase + nf * 8 + 2 * tig;
            if (i0 < j0     || i0 - j0 > WW)     S[nf][0] = -1e9f;
            if (i0 < j0 + 1 || i0 - j0 - 1 > WW) S[nf][1] = -1e9f;
            if (i1 < j0     || i1 - j0 > WW)     S[nf][2] = -1e9f;
            if (i1 < j0 + 1 || i1 - j0 - 1 > WW) S[nf][3] = -1e9f;
            rmax0 = fmaxf(rmax0, fmaxf(S[nf][0], S[nf][1]));
            rmax1 = fmaxf(rmax1, fmaxf(S[nf][2], S[nf][3]));
        }
        rmax0 = fmaxf(rmax0, __shfl_xor_sync(0xffffffffu, rmax0, 1));
        rmax0 = fmaxf(rmax0, __shfl_xor_sync(0xffffffffu, rmax0, 2));
        rmax1 = fmaxf(rmax1, __shfl_xor_sync(0xffffffffu, rmax1, 1));
        rmax1 = fmaxf(rmax1, __shfl_xor_sync(0xffffffffu, rmax1, 2));
        float mn0 = fmaxf(m0, rmax0), mn1 = fmaxf(m1, rmax1);
        float cor0 = __expf(m0 - mn0), cor1 = __expf(m1 - mn1);
        m0 = mn0; m1 = mn1;
        float ls0 = 0.f, ls1 = 0.f;
        #pragma unroll
        for (int nf = 0; nf < 8; nf++) {
            float p0 = __expf(S[nf][0] - mn0);
            float p1 = __expf(S[nf][1] - mn0);
            float p2 = __expf(S[nf][2] - mn1);
            float p3 = __expf(S[nf][3] - mn1);
            ls0 += p0 + p1;
            ls1 += p2 + p3;
            int jp = nf * 4 + tig;   // jj-pair index (jj = nf*8 + 2tig)
            Ps[gid * PST + jp]       = packh2(p0, p1);
            Ps[(gid + 8) * PST + jp] = packh2(p2, p3);
        }
        l0 = l0 * cor0 + ls0;
        l1 = l1 * cor1 + ls1;
        #pragma unroll
        for (int nf = 0; nf < 8; nf++) {
            O[nf][0] *= cor0; O[nf][1] *= cor0;
            O[nf][2] *= cor1; O[nf][3] *= cor1;
        }
        __syncwarp();
        unsigned pa[4][4];
        #pragma unroll
        for (int s = 0; s < 4; s++) {
            uint2 u0 = *(const uint2*)&Ps[gid * PST + s * 8 + 2 * tig];
            uint2 u1 = *(const uint2*)&Ps[(gid + 8) * PST + s * 8 + 2 * tig];
            pa[s][0] = u0.x; pa[s][1] = u1.x; pa[s][2] = u0.y; pa[s][3] = u1.y;
        }
        #pragma unroll
        for (int nd = 0; nd < 8; nd++) {
            int n = nd * 8 + gid;
            #pragma unroll
            for (int s = 0; s < 4; s++) {
                int jbl = jbase + s * 16;
                if (jbl > Imax || jbl + 15 < Imin - WW) continue;
                unsigned b0 = smU[VS_OFF + (c * 32 + s * 8 + 2 * tig) * VST + n];
                unsigned b1 = smU[VS_OFF + (c * 32 + s * 8 + 2 * tig + 1) * VST + n];
                mma_f16(O[nd], pa[s][0], pa[s][1], pa[s][2], pa[s][3], b0, b1);
            }
        }
        __syncwarp();
    }

    l0 += __shfl_xor_sync(0xffffffffu, l0, 1);
    l0 += __shfl_xor_sync(0xffffffffu, l0, 2);
    l1 += __shfl_xor_sync(0xffffffffu, l1, 1);
    l1 += __shfl_xor_sync(0xffffffffu, l1, 2);
    float inv0 = 1.f / l0, inv1 = 1.f / l1;

    __half* op0 = outp + (rowbase + i0) * INNER + head * DH;
    __half* op1 = outp + (rowbase + i1) * INNER + head * DH;
    #pragma unroll
    for (int nd = 0; nd < 8; nd++) {
        int d0 = nd * 8 + 2 * tig;
        *(__half2*)&op0[d0] = __floats2half2_rn(O[nd][0] * inv0, O[nd][1] * inv0);
        *(__half2*)&op1[d0] = __floats2half2_rn(O[nd][2] * inv1, O[nd][3] * inv1);
    }
}

// ---------------- Final LN + logits + slice ----------------
__global__ void final_kernel(const float* __restrict__ gg, const float* __restrict__ bb,
                             const float* __restrict__ wl, float* __restrict__ out) {
    int row = blockIdx.x, c = threadIdx.x;
    int n = row & (N_ - 1);
    if (n < SLACK || n >= N_ - SLACK) return;
    float v = g_h[(size_t)row * LD + c];
    __shared__ float sh[16];
    __shared__ float stat[2];
    float s = v, sq = v * v;
    #pragma unroll
    for (int o = 16; o > 0; o >>= 1) {
        s  += __shfl_down_sync(0xffffffffu, s, o);
        sq += __shfl_down_sync(0xffffffffu, sq, o);
    }
    if ((c & 31) == 0) { sh[c >> 5] = s; sh[8 + (c >> 5)] = sq; }
    __syncthreads();
    if (c == 0) {
        float S = 0.f, SQ = 0.f;
        #pragma unroll
        for (int i = 0; i < 8; i++) { S += sh[i]; SQ += sh[8 + i]; }
        float mean = S * (1.f / LD);
        stat[0] = mean;
        stat[1] = rsqrtf(SQ * (1.f / LD) - mean * mean + 1e-5f);
    }
    __syncthreads();
    float contrib = ((v - stat[0]) * stat[1] * gg[c] + bb[c]) * wl[c];
    #pragma unroll
    for (int o = 16; o > 0; o >>= 1)
        contrib += __shfl_down_sync(0xffffffffu, contrib, o);
    __syncthreads();
    if ((c & 31) == 0) sh[c >> 5] = contrib;
    __syncthreads();
    if (c == 0) {
        float T = 0.f;
        #pragma unroll
        for (int i = 0; i < 8; i++) T += sh[i];
        int bidx = row >> 12;
        out[bidx * (N_ - 2 * SLACK) + (n - SLACK)] = T;
    }
}

// ---------------- Launch ----------------
extern "C" void kernel_launch(void* const* d_in, const int* in_sizes, int n_in,
                              void* d_out, int out_size) {
    const float* x        = (const float*)d_in[0];
    const float* W_exp    = (const float*)d_in[1];
    const float* b_exp    = (const float*)d_in[2];
    const float* pos_emb  = (const float*)d_in[3];
    const float* ln_att_g = (const float*)d_in[4];
    const float* ln_att_b = (const float*)d_in[5];
    const float* Wqkv     = (const float*)d_in[6];
    const float* Wout     = (const float*)d_in[7];
    const float* ln_ff_g  = (const float*)d_in[8];
    const float* ln_ff_b  = (const float*)d_in[9];
    const float* W1       = (const float*)d_in[10];
    const float* b1       = (const float*)d_in[11];
    const float* W2       = (const float*)d_in[12];
    const float* b2       = (const float*)d_in[13];
    const float* ln_f_g   = (const float*)d_in[14];
    const float* ln_f_b   = (const float*)d_in[15];
    const float* W_logits = (const float*)d_in[16];
    float* out = (float*)d_out;

    float *ph;
    __half *pyh, *pqkvh, *poh, *pffh;
    unsigned *pwp;
    cudaGetSymbolAddress((void**)&ph,    g_h);
    cudaGetSymbolAddress((void**)&pyh,   g_yh);
    cudaGetSymbolAddress((void**)&pqkvh, g_qkvh);
    cudaGetSymbolAddress((void**)&poh,   g_oh);
    cudaGetSymbolAddress((void**)&pffh,  g_ffh);
    cudaGetSymbolAddress((void**)&pwp,   g_wp);

    cudaFuncSetAttribute(attn_mma_kernel, cudaFuncAttributeMaxDynamicSharedMemorySize, ATTN_SMEM);
    cudaFuncSetAttribute(hgemm<0>, cudaFuncAttributeMaxDynamicSharedMemorySize, HG_SMEM);
    cudaFuncSetAttribute(hgemm<1>, cudaFuncAttributeMaxDynamicSharedMemorySize, HG_SMEM);
    cudaFuncSetAttribute(hgemm<2>, cudaFuncAttributeMaxDynamicSharedMemorySize, HG_SMEM);
    cudaFuncSetAttribute(hgemm<3>, cudaFuncAttributeMaxDynamicSharedMemorySize, HG_SMEM);

    rope_table_kernel<<<(N_ * 32 + 255) / 256, 256>>>();
    pack_w_kernel<<<(786432 + 255) / 256, 256>>>(Wqkv, pwp + WQKV_OFF, DEPTH * LD / 2, QKVW);
    pack_w_kernel<<<(262144 + 255) / 256, 256>>>(Wout, pwp + WOUT_OFF, DEPTH * INNER / 2, LD);
    pack_w_kernel<<<(524288 + 255) / 256, 256>>>(W1,   pwp + W1_OFF,   DEPTH * LD / 2, FF);
    pack_w_kernel<<<(524288 + 255) / 256, 256>>>(W2,   pwp + W2_OFF,   DEPTH * FF / 2, LD);
    expand_kernel<<<R_, LD>>>(x, W_exp, b_exp, pos_emb);

    for (int l = 0; l < DEPTH; ++l) {
        ln_kernel<<<R_, LD>>>(ph, pyh, ln_att_g + l * LD, ln_att_b + l * LD);
        hgemm<0><<<dim3(QKVW / 128, R_ / 128), 256, HG_SMEM>>>(
            pyh, pwp + WQKV_OFF + (size_t)l * (LD / 2) * QKVW, pqkvh, nullptr, QKVW, LD);
        attn_mma_kernel<<<dim3(N_ / WW, H_, B_), 256, ATTN_SMEM>>>(pqkvh, poh);
        hgemm<2><<<dim3(LD / 128, R_ / 128), 256, HG_SMEM>>>(
            poh, pwp + WOUT_OFF + (size_t)l * (INNER / 2) * LD, ph, nullptr, LD, INNER);
        ln_kernel<<<R_, LD>>>(ph, pyh, ln_ff_g + l * LD, ln_ff_b + l * LD);
        hgemm<1><<<dim3(FF / 128, R_ / 128), 256, HG_SMEM>>>(
            pyh, pwp + W1_OFF + (size_t)l * (LD / 2) * FF, pffh, b1 + (size_t)l * FF, FF, LD);
        hgemm<3><<<dim3(LD / 128, R_ / 128), 256, HG_SMEM>>>(
            pffh, pwp + W2_OFF + (size_t)l * (FF / 2) * LD, ph, b2 + (size_t)l * LD, LD, FF);
    }

    final_kernel<<<R_, LD>>>(ln_f_g, ln_f_b, W_logits, out);
}

// round 16
// speedup vs baseline: 1.1718x; 1.0918x over previous
#include <cuda_runtime.h>
#include <cuda_fp16.h>
#include <math.h>

// ---------------- Problem constants ----------------
constexpr int B_    = 16;
constexpr int N_    = 4096;
constexpr int LD    = 256;
constexpr int H_    = 8;
constexpr int DH    = 64;
constexpr int WW    = 128;
constexpr int INNER = 512;   // H_*DH
constexpr int DEPTH = 4;
constexpr int FF    = 1024;
constexpr int SLACK = 50;
constexpr int R_    = B_ * N_;          // 65536 rows
constexpr int QKVW  = 3 * INNER;        // 1536

// ---------------- Scratch ----------------
__device__ float  g_h[(size_t)R_ * LD];          // fp32 residual stream
__device__ __half g_yh[(size_t)R_ * LD];         // LN output (GEMM A)
__device__ __half g_qkvh[(size_t)R_ * QKVW];     // qkv fp16
__device__ __half g_oh[(size_t)R_ * INNER];      // attention out fp16
__device__ __half g_ffh[(size_t)R_ * FF];        // FF hidden fp16
__device__ unsigned g_wp[2097152];               // k-pair-packed fp16 weights
__device__ float  g_cos[(size_t)N_ * 32];
__device__ float  g_sin[(size_t)N_ * 32];
// word offsets into g_wp
constexpr size_t WQKV_OFF = 0;
constexpr size_t WOUT_OFF = 786432;
constexpr size_t W1_OFF   = 1048576;
constexpr size_t W2_OFF   = 1572864;

__device__ __forceinline__ unsigned packh2(float lo, float hi) {
    __half2 h = __floats2half2_rn(lo, hi);
    return *reinterpret_cast<unsigned*>(&h);
}

__device__ __forceinline__ void mma_f16(float* c, unsigned a0, unsigned a1,
                                        unsigned a2, unsigned a3,
                                        unsigned b0, unsigned b1) {
    asm volatile("mma.sync.aligned.m16n8k16.row.col.f32.f16.f16.f32 "
                 "{%0,%1,%2,%3}, {%4,%5,%6,%7}, {%8,%9}, {%0,%1,%2,%3};\n"
                 : "+f"(c[0]), "+f"(c[1]), "+f"(c[2]), "+f"(c[3])
                 : "r"(a0), "r"(a1), "r"(a2), "r"(a3), "r"(b0), "r"(b1));
}

__device__ __forceinline__ void cp16(void* smem, const void* g) {
    unsigned sa = (unsigned)__cvta_generic_to_shared(smem);
    asm volatile("cp.async.ca.shared.global [%0], [%1], 16;\n" :: "r"(sa), "l"(g));
}

// ---------------- RoPE table ----------------
__global__ void rope_table_kernel() {
    int idx = blockIdx.x * blockDim.x + threadIdx.x;
    if (idx >= N_ * 32) return;
    int n = idx >> 5, d = idx & 31;
    float invf = (float)(1.0 / pow(10000.0, (double)(2 * d) / 64.0));
    float angf = (float)n * invf;
    double a = (double)angf;
    g_cos[idx] = (float)cos(a);
    g_sin[idx] = (float)sin(a);
}

// ---------------- weight packing: W[K][N] fp32 -> out[K/2][N] half2-words ----------------
__global__ void pack_w_kernel(const float* __restrict__ W, unsigned* __restrict__ out,
                              int rows2, int N) {
    int idx = blockIdx.x * blockDim.x + threadIdx.x;
    if (idx >= rows2 * N) return;
    int kp = idx / N, n = idx - kp * N;
    out[idx] = packh2(W[(size_t)(2 * kp) * N + n], W[(size_t)(2 * kp + 1) * N + n]);
}

// ---------------- Expand ----------------
__global__ void expand_kernel(const float* __restrict__ x, const float* __restrict__ We,
                              const float* __restrict__ be, const float* __restrict__ pe) {
    int row = blockIdx.x;
    int c   = threadIdx.x;
    int n   = row & (N_ - 1);
    float x0 = x[row * 2 + 0], x1 = x[row * 2 + 1];
    g_h[(size_t)row * LD + c] = x0 * We[c] + x1 * We[LD + c] + be[c] + pe[n * LD + c];
}

// ---------------- LayerNorm (fp32 in, fp16 out) — used once for layer 0 ----------------
__global__ void ln_kernel(const float* __restrict__ src, __half* __restrict__ dst,
                          const float* __restrict__ gg, const float* __restrict__ bb) {
    int row = blockIdx.x, c = threadIdx.x;
    float v = src[(size_t)row * LD + c];
    float s = v, sq = v * v;
    #pragma unroll
    for (int o = 16; o > 0; o >>= 1) {
        s  += __shfl_down_sync(0xffffffffu, s, o);
        sq += __shfl_down_sync(0xffffffffu, sq, o);
    }
    __shared__ float sh[16];
    __shared__ float stat[2];
    if ((c & 31) == 0) { sh[c >> 5] = s; sh[8 + (c >> 5)] = sq; }
    __syncthreads();
    if (c == 0) {
        float S = 0.f, SQ = 0.f;
        #pragma unroll
        for (int i = 0; i < 8; i++) { S += sh[i]; SQ += sh[8 + i]; }
        float mean = S * (1.f / LD);
        stat[0] = mean;
        stat[1] = rsqrtf(SQ * (1.f / LD) - mean * mean + 1e-5f);
    }
    __syncthreads();
    dst[(size_t)row * LD + c] = __float2half_rn((v - stat[0]) * stat[1] * gg[c] + bb[c]);
}

// ---------------- fp16 GEMM: BK=32, m16n8k16, 3-stage cp.async (R6, unchanged) ----------------
constexpr int AST = 20;
constexpr int BST = 132;
constexpr int HG_STAGES = 3;
constexpr int AS_W = 128 * AST;
constexpr int BS_W = 16 * BST;
constexpr int HG_SMEM = HG_STAGES * (AS_W + BS_W) * 4;   // 56064 B

template <int EPI>   // 0 = half store, 1 = +bias GELU half store
__global__ __launch_bounds__(256, 2)
void hgemm(const __half* __restrict__ A, const unsigned* __restrict__ Bp,
           void* __restrict__ Cv, const float* __restrict__ bias, int Nc, int K) {
    extern __shared__ unsigned smw[];
    unsigned* AsBase = smw;
    unsigned* BsBase = smw + HG_STAGES * AS_W;

    int tid  = threadIdx.x;
    int row0 = blockIdx.y * 128;
    int col0 = blockIdx.x * 128;
    int lane = tid & 31, w = tid >> 5;
    int gid  = lane >> 2, tig = lane & 3;
    int wr   = w & 1;
    int wc   = w >> 1;

    int ar = tid >> 1;
    int ac = tid & 1;
    int bk = tid >> 5;
    int bc = tid & 31;

    const __half* ApS = A + (size_t)(row0 + ar) * K;
    const unsigned* BpS = Bp + (size_t)bk * Nc + col0 + bc * 4;

    float acc[4][4][4];
    #pragma unroll
    for (int mi = 0; mi < 4; mi++)
        #pragma unroll
        for (int ni = 0; ni < 4; ni++)
            #pragma unroll
            for (int e = 0; e < 4; e++) acc[mi][ni][e] = 0.f;

    int NT = K >> 5;

    auto stage = [&](int kti, int buf) {
        unsigned* Asb = AsBase + buf * AS_W;
        unsigned* Bsb = BsBase + buf * BS_W;
        const __half* as = ApS + kti * 32 + ac * 8;
        cp16(&Asb[ar * AST + ac * 4], as);
        cp16(&Asb[ar * AST + ac * 4 + 8], as + 16);
        const unsigned* bs = BpS + (size_t)kti * 16 * Nc;
        cp16(&Bsb[bk * BST + bc * 4], bs);
        cp16(&Bsb[(bk + 8) * BST + bc * 4], bs + (size_t)8 * Nc);
    };

    stage(0, 0);
    asm volatile("cp.async.commit_group;\n");
    stage(1, 1);
    asm volatile("cp.async.commit_group;\n");

    for (int it = 0; it < NT; it++) {
        int cur = it % HG_STAGES;
        asm volatile("cp.async.wait_group 1;\n");
        __syncthreads();
        if (it + 2 < NT) stage(it + 2, (it + 2) % HG_STAGES);
        asm volatile("cp.async.commit_group;\n");

        const unsigned* Asb = AsBase + cur * AS_W;
        const unsigned* Bsb = BsBase + cur * BS_W;

        #pragma unroll
        for (int s = 0; s < 2; s++) {
            uint2 fA[4][2];
            #pragma unroll
            for (int mi = 0; mi < 4; mi++) {
                int m = wr * 64 + mi * 16 + gid;
                fA[mi][0] = *(const uint2*)&Asb[m * AST + s * 8 + 2 * tig];
                fA[mi][1] = *(const uint2*)&Asb[(m + 8) * AST + s * 8 + 2 * tig];
            }
            #pragma unroll
            for (int ni = 0; ni < 4; ni++) {
                int n = wc * 32 + ni * 8 + gid;
                unsigned b0 = Bsb[(s * 8 + 2 * tig) * BST + n];
                unsigned b1 = Bsb[(s * 8 + 2 * tig + 1) * BST + n];
                #pragma unroll
                for (int mi = 0; mi < 4; mi++) {
                    mma_f16(acc[mi][ni], fA[mi][0].x, fA[mi][1].x,
                            fA[mi][0].y, fA[mi][1].y, b0, b1);
                }
            }
        }
    }

    __half* Ch = (__half*)Cv;
    #pragma unroll
    for (int mi = 0; mi < 4; mi++) {
        int ra = row0 + wr * 64 + mi * 16 + gid;
        #pragma unroll
        for (int ni = 0; ni < 4; ni++) {
            int cc = col0 + wc * 32 + ni * 8 + tig * 2;
            #pragma unroll
            for (int half = 0; half < 2; half++) {
                int r = ra + half * 8;
                float v0 = acc[mi][ni][half * 2 + 0];
                float v1 = acc[mi][ni][half * 2 + 1];
                size_t off = (size_t)r * Nc + cc;
                if (EPI == 0) {
                    *(__half2*)&Ch[off] = __floats2half2_rn(v0, v1);
                } else {
                    v0 += bias[cc];
                    v1 += bias[cc + 1];
                    v0 = 0.5f * v0 * (1.f + erff(v0 * 0.70710678118654752f));
                    v1 = 0.5f * v1 * (1.f + erff(v1 * 0.70710678118654752f));
                    *(__half2*)&Ch[off] = __floats2half2_rn(v0, v1);
                }
            }
        }
    }
}

// ---------------- fused GEMM(N=256) + residual + LayerNorm ----------------
// Block: 64 rows x 256 cols, 8 warps (warp w owns cols [32w, 32w+32)).
// out_row = g_h_row + A@B (+bias); writes g_h; if DO_LN writes yh = LN(out)*g+b (fp16).
constexpr int FBST = 260;                 // B smem row stride (256 + 4)
constexpr int FAS_W = 64 * AST;           // 1280 words/stage
constexpr int FBS_W = 16 * FBST;          // 4160 words/stage
constexpr int FL_SMEM = HG_STAGES * (FAS_W + FBS_W) * 4;   // 65280 B

template <bool BIAS, bool DO_LN>
__global__ __launch_bounds__(256, 2)
void hgemm_ln(const __half* __restrict__ A, const unsigned* __restrict__ Bp,
              float* __restrict__ Hh, const float* __restrict__ bias,
              const float* __restrict__ lng, const float* __restrict__ lnb,
              __half* __restrict__ Yh, int K) {
    extern __shared__ unsigned smw[];
    unsigned* AsBase = smw;
    unsigned* BsBase = smw + HG_STAGES * FAS_W;
    __shared__ float red_s[64][9];
    __shared__ float red_q[64][9];
    __shared__ float stats[64][2];

    int tid  = threadIdx.x;
    int row0 = blockIdx.x * 64;
    int lane = tid & 31, w = tid >> 5;
    int gid  = lane >> 2, tig = lane & 3;

    int ar = tid >> 2;        // 0..63 A row
    int aq = tid & 3;         // k quad
    int bk = tid >> 5;        // 0..7 (+8)
    int bc = tid & 31;        // 4-word col group (two halves: +0 / +128)

    const __half* ApS = A + (size_t)(row0 + ar) * K;
    const unsigned* BpS = Bp + (size_t)bk * LD + bc * 4;

    float acc[4][4][4];
    #pragma unroll
    for (int mi = 0; mi < 4; mi++)
        #pragma unroll
        for (int ni = 0; ni < 4; ni++)
            #pragma unroll
            for (int e = 0; e < 4; e++) acc[mi][ni][e] = 0.f;

    int NT = K >> 5;

    auto stage = [&](int kti, int buf) {
        unsigned* Asb = AsBase + buf * FAS_W;
        unsigned* Bsb = BsBase + buf * FBS_W;
        cp16(&Asb[ar * AST + aq * 4], ApS + kti * 32 + aq * 8);
        const unsigned* bs = BpS + (size_t)kti * 16 * LD;
        cp16(&Bsb[bk * FBST + bc * 4], bs);
        cp16(&Bsb[bk * FBST + bc * 4 + 128], bs + 128);
        cp16(&Bsb[(bk + 8) * FBST + bc * 4], bs + (size_t)8 * LD);
        cp16(&Bsb[(bk + 8) * FBST + bc * 4 + 128], bs + (size_t)8 * LD + 128);
    };

    stage(0, 0);
    asm volatile("cp.async.commit_group;\n");
    stage(1, 1);
    asm volatile("cp.async.commit_group;\n");

    for (int it = 0; it < NT; it++) {
        int cur = it % HG_STAGES;
        asm volatile("cp.async.wait_group 1;\n");
        __syncthreads();
        if (it + 2 < NT) stage(it + 2, (it + 2) % HG_STAGES);
        asm volatile("cp.async.commit_group;\n");

        const unsigned* Asb = AsBase + cur * FAS_W;
        const unsigned* Bsb = BsBase + cur * FBS_W;

        #pragma unroll
        for (int s = 0; s < 2; s++) {
            uint2 fA[4][2];
            #pragma unroll
            for (int mi = 0; mi < 4; mi++) {
                int m = mi * 16 + gid;
                fA[mi][0] = *(const uint2*)&Asb[m * AST + s * 8 + 2 * tig];
                fA[mi][1] = *(const uint2*)&Asb[(m + 8) * AST + s * 8 + 2 * tig];
            }
            #pragma unroll
            for (int ni = 0; ni < 4; ni++) {
                int n = w * 32 + ni * 8 + gid;
                unsigned b0 = Bsb[(s * 8 + 2 * tig) * FBST + n];
                unsigned b1 = Bsb[(s * 8 + 2 * tig + 1) * FBST + n];
                #pragma unroll
                for (int mi = 0; mi < 4; mi++) {
                    mma_f16(acc[mi][ni], fA[mi][0].x, fA[mi][1].x,
                            fA[mi][0].y, fA[mi][1].y, b0, b1);
                }
            }
        }
    }

    // ---- epilogue: residual add, write h, row-LN, write yh ----
    float bv[8], gam[8], bet[8];
    #pragma unroll
    for (int ni = 0; ni < 4; ni++) {
        int cc = w * 32 + ni * 8 + tig * 2;
        if (BIAS) { bv[2*ni] = bias[cc]; bv[2*ni+1] = bias[cc+1]; }
        if (DO_LN) {
            gam[2*ni]   = lng[cc];
            gam[2*ni+1] = lng[cc+1];
            bet[2*ni]   = lnb[cc];
            bet[2*ni+1] = lnb[cc+1];
        }
    }

    #pragma unroll
    for (int mi = 0; mi < 4; mi++) {
        #pragma unroll
        for (int half = 0; half < 2; half++) {
            int row = row0 + mi * 16 + gid + half * 8;
            float ps = 0.f, pq = 0.f;
            #pragma unroll
            for (int ni = 0; ni < 4; ni++) {
                int cc = w * 32 + ni * 8 + tig * 2;
                size_t off = (size_t)row * LD + cc;
                float2 hres = *(float2*)&Hh[off];
                float v0 = acc[mi][ni][half * 2 + 0] + hres.x;
                float v1 = acc[mi][ni][half * 2 + 1] + hres.y;
                if (BIAS) { v0 += bv[2*ni]; v1 += bv[2*ni+1]; }
                acc[mi][ni][half * 2 + 0] = v0;
                acc[mi][ni][half * 2 + 1] = v1;
                float2 hw = {v0, v1};
                *(float2*)&Hh[off] = hw;
                if (DO_LN) { ps += v0 + v1; pq += v0 * v0 + v1 * v1; }
            }
            if (DO_LN) {
                ps += __shfl_xor_sync(0xffffffffu, ps, 1);
                ps += __shfl_xor_sync(0xffffffffu, ps, 2);
                pq += __shfl_xor_sync(0xffffffffu, pq, 1);
                pq += __shfl_xor_sync(0xffffffffu, pq, 2);
                if (tig == 0) {
                    red_s[mi * 16 + gid + half * 8][w] = ps;
                    red_q[mi * 16 + gid + half * 8][w] = pq;
                }
            }
        }
    }

    if (DO_LN) {
        __syncthreads();
        if (tid < 64) {
            float S = 0.f, Q = 0.f;
            #pragma unroll
            for (int i = 0; i < 8; i++) { S += red_s[tid][i]; Q += red_q[tid][i]; }
            float mean = S * (1.f / LD);
            stats[tid][0] = mean;
            stats[tid][1] = rsqrtf(Q * (1.f / LD) - mean * mean + 1e-5f);
        }
        __syncthreads();
        #pragma unroll
        for (int mi = 0; mi < 4; mi++) {
            #pragma unroll
            for (int half = 0; half < 2; half++) {
                int ml = mi * 16 + gid + half * 8;
                float mean = stats[ml][0], rstd = stats[ml][1];
                int row = row0 + ml;
                #pragma unroll
                for (int ni = 0; ni < 4; ni++) {
                    int cc = w * 32 + ni * 8 + tig * 2;
                    float y0 = (acc[mi][ni][half*2+0] - mean) * rstd * gam[2*ni]   + bet[2*ni];
                    float y1 = (acc[mi][ni][half*2+1] - mean) * rstd * gam[2*ni+1] + bet[2*ni+1];
                    *(__half2*)&Yh[(size_t)row * LD + cc] = __floats2half2_rn(y0, y1);
                }
            }
        }
    }
}

// ---------------- fp16 tensor-core flash local attention (R6, unchanged) ----------------
constexpr int KST = 260;
constexpr int QST = 34;
constexpr int VST = 68;
constexpr int PST = 36;
constexpr int KS_OFF = 0;
constexpr int QS_OFF = 32 * KST;
constexpr int VS_OFF = QS_OFF + 128 * QST;
constexpr int PS_OFF = VS_OFF + 128 * VST;
constexpr int ATTN_SMEM = (PS_OFF + 8 * 16 * PST) * 4;

__global__ __launch_bounds__(256)
void attn_mma_kernel(const __half* __restrict__ qkv, __half* __restrict__ outp) {
    extern __shared__ unsigned smU[];

    int w = blockIdx.x, head = blockIdx.y, b = blockIdx.z;
    int tid  = threadIdx.x;
    int lane = tid & 31;
    int wm   = tid >> 5;
    int gid  = lane >> 2, tig = lane & 3;
    int qbase = w * WW;
    size_t rowbase = (size_t)b * N_;

    {
        int jj = tid;
        int p = qbase - WW + jj;
        float kv[64];
        if (p >= 0) {
            const __half2* kp2 = (const __half2*)(qkv + (rowbase + p) * QKVW + INNER + head * DH);
            float raw[64];
            #pragma unroll
            for (int i = 0; i < 32; i++) {
                float2 f = __half22float2(kp2[i]);
                raw[2 * i] = f.x; raw[2 * i + 1] = f.y;
            }
            #pragma unroll
            for (int d = 0; d < 32; d++) {
                float cs = g_cos[p * 32 + d], sn = g_sin[p * 32 + d];
                kv[d]      = raw[d] * cs - raw[d + 32] * sn;
                kv[d + 32] = raw[d + 32] * cs + raw[d] * sn;
            }
        } else {
            #pragma unroll
            for (int d = 0; d < 64; d++) kv[d] = 0.f;
        }
        #pragma unroll
        for (int dp = 0; dp < 32; dp++)
            smU[KS_OFF + dp * KST + jj] = packh2(kv[2 * dp], kv[2 * dp + 1]);
    }
    {
        int jp = tid >> 1;
        int dh = (tid & 1) * 32;
        int p0 = qbase - WW + 2 * jp;
        unsigned* vrow = smU + VS_OFF + jp * VST + dh;
        if (p0 >= 0) {
            const __half2* vA = (const __half2*)(qkv + (rowbase + p0) * QKVW + 2 * INNER + head * DH + dh);
            const __half2* vB = (const __half2*)(qkv + (rowbase + p0 + 1) * QKVW + 2 * INNER + head * DH + dh);
            #pragma unroll
            for (int i = 0; i < 16; i++) {
                float2 fa = __half22float2(vA[i]);
                float2 fb = __half22float2(vB[i]);
                vrow[2 * i]     = packh2(fa.x, fb.x);
                vrow[2 * i + 1] = packh2(fa.y, fb.y);
            }
        } else {
            #pragma unroll
            for (int i = 0; i < 32; i++) vrow[i] = 0u;
        }
    }
    if (tid < 128) {
        int r = tid;
        int i = qbase + r;
        const __half2* qp2 = (const __half2*)(qkv + (rowbase + i) * QKVW + head * DH);
        float raw[64], qv[64];
        #pragma unroll
        for (int ii = 0; ii < 32; ii++) {
            float2 f = __half22float2(qp2[ii]);
            raw[2 * ii] = f.x; raw[2 * ii + 1] = f.y;
        }
        #pragma unroll
        for (int d = 0; d < 32; d++) {
            float cs = g_cos[i * 32 + d], sn = g_sin[i * 32 + d];
            qv[d]      = (raw[d] * cs - raw[d + 32] * sn) * 0.125f;
            qv[d + 32] = (raw[d + 32] * cs + raw[d] * sn) * 0.125f;
        }
        #pragma unroll
        for (int j = 0; j < 32; j++)
            smU[QS_OFF + r * QST + j] = packh2(qv[2 * j], qv[2 * j + 1]);
    }
    __syncthreads();

    unsigned qa[4][4];
    {
        int rA = wm * 16 + gid, rB = rA + 8;
        #pragma unroll
        for (int s = 0; s < 4; s++) {
            uint2 u0 = *(const uint2*)&smU[QS_OFF + rA * QST + s * 8 + 2 * tig];
            uint2 u1 = *(const uint2*)&smU[QS_OFF + rB * QST + s * 8 + 2 * tig];
            qa[s][0] = u0.x; qa[s][1] = u1.x; qa[s][2] = u0.y; qa[s][3] = u1.y;
        }
    }

    float O[8][4];
    #pragma unroll
    for (int nf = 0; nf < 8; nf++)
        #pragma unroll
        for (int e = 0; e < 4; e++) O[nf][e] = 0.f;
    float m0 = -1e30f, m1 = -1e30f, l0 = 0.f, l1 = 0.f;

    unsigned* Ps = smU + PS_OFF + wm * 16 * PST;
    int Imin = qbase + wm * 16;
    int Imax = Imin + 15;
    int i0 = Imin + gid;
    int i1 = i0 + 8;

    int clo = wm >> 2, chi = clo + 2;
    if (w == 0) clo = 2;

    for (int c = clo; c <= chi; c++) {
        int jbase = qbase - WW + c * 64;
        float S[8][4];
        #pragma unroll
        for (int nf = 0; nf < 8; nf++)
            #pragma unroll
            for (int e = 0; e < 4; e++) S[nf][e] = 0.f;
        #pragma unroll
        for (int nf = 0; nf < 8; nf++) {
            int jlo = jbase + nf * 8;
            if (jlo > Imax || jlo + 7 < Imin - WW) continue;
            int n = c * 64 + nf * 8 + gid;
            #pragma unroll
            for (int s = 0; s < 4; s++) {
                unsigned b0 = smU[KS_OFF + (s * 8 + 2 * tig) * KST + n];
                unsigned b1 = smU[KS_OFF + (s * 8 + 2 * tig + 1) * KST + n];
                mma_f16(S[nf], qa[s][0], qa[s][1], qa[s][2], qa[s][3], b0, b1);
            }
        }
        float rmax0 = -1e30f, rmax1 = -1e30f;
        #pragma unroll
        for (int nf = 0; nf < 8; nf++) {
            int j0 = jbase + nf * 8 + 2 * tig;
            if (i0 < j0     || i0 - j0 > WW)     S[nf][0] = -1e9f;
            if (i0 < j0 + 1 || i0 - j0 - 1 > WW) S[nf][1] = -1e9f;
            if (i1 < j0     || i1 - j0 > WW)     S[nf][2] = -1e9f;
            if (i1 < j0 + 1 || i1 - j0 - 1 > WW) S[nf][3] = -1e9f;
            rmax0 = fmaxf(rmax0, fmaxf(S[nf][0], S[nf][1]));
            rmax1 = fmaxf(rmax1, fmaxf(S[nf][2], S[nf][3]));
        }
        rmax0 = fmaxf(rmax0, __shfl_xor_sync(0xffffffffu, rmax0, 1));
        rmax0 = fmaxf(rmax0, __shfl_xor_sync(0xffffffffu, rmax0, 2));
        rmax1 = fmaxf(rmax1, __shfl_xor_sync(0xffffffffu, rmax1, 1));
        rmax1 = fmaxf(rmax1, __shfl_xor_sync(0xffffffffu, rmax1, 2));
        float mn0 = fmaxf(m0, rmax0), mn1 = fmaxf(m1, rmax1);
        float cor0 = __expf(m0 - mn0), cor1 = __expf(m1 - mn1);
        m0 = mn0; m1 = mn1;
        float ls0 = 0.f, ls1 = 0.f;
        #pragma unroll
        for (int nf = 0; nf < 8; nf++) {
            float p0 = __expf(S[nf][0] - mn0);
            float p1 = __expf(S[nf][1] - mn0);
            float p2 = __expf(S[nf][2] - mn1);
            float p3 = __expf(S[nf][3] - mn1);
            ls0 += p0 + p1;
            ls1 += p2 + p3;
            int jp = nf * 4 + tig;
            Ps[gid * PST + jp]       = packh2(p0, p1);
            Ps[(gid + 8) * PST + jp] = packh2(p2, p3);
        }
        l0 = l0 * cor0 + ls0;
        l1 = l1 * cor1 + ls1;
        #pragma unroll
        for (int nf = 0; nf < 8; nf++) {
            O[nf][0] *= cor0; O[nf][1] *= cor0;
            O[nf][2] *= cor1; O[nf][3] *= cor1;
        }
        __syncwarp();
        unsigned pa[4][4];
        #pragma unroll
        for (int s = 0; s < 4; s++) {
            uint2 u0 = *(const uint2*)&Ps[gid * PST + s * 8 + 2 * tig];
            uint2 u1 = *(const uint2*)&Ps[(gid + 8) * PST + s * 8 + 2 * tig];
            pa[s][0] = u0.x; pa[s][1] = u1.x; pa[s][2] = u0.y; pa[s][3] = u1.y;
        }
        #pragma unroll
        for (int nd = 0; nd < 8; nd++) {
            int n = nd * 8 + gid;
            #pragma unroll
            for (int s = 0; s < 4; s++) {
                int jbl = jbase + s * 16;
                if (jbl > Imax || jbl + 15 < Imin - WW) continue;
                unsigned b0 = smU[VS_OFF + (c * 32 + s * 8 + 2 * tig) * VST + n];
                unsigned b1 = smU[VS_OFF + (c * 32 + s * 8 + 2 * tig + 1) * VST + n];
                mma_f16(O[nd], pa[s][0], pa[s][1], pa[s][2], pa[s][3], b0, b1);
            }
        }
        __syncwarp();
    }

    l0 += __shfl_xor_sync(0xffffffffu, l0, 1);
    l0 += __shfl_xor_sync(0xffffffffu, l0, 2);
    l1 += __shfl_xor_sync(0xffffffffu, l1, 1);
    l1 += __shfl_xor_sync(0xffffffffu, l1, 2);
    float inv0 = 1.f / l0, inv1 = 1.f / l1;

    __half* op0 = outp + (rowbase + i0) * INNER + head * DH;
    __half* op1 = outp + (rowbase + i1) * INNER + head * DH;
    #pragma unroll
    for (int nd = 0; nd < 8; nd++) {
        int d0 = nd * 8 + 2 * tig;
        *(__half2*)&op0[d0] = __floats2half2_rn(O[nd][0] * inv0, O[nd][1] * inv0);
        *(__half2*)&op1[d0] = __floats2half2_rn(O[nd][2] * inv1, O[nd][3] * inv1);
    }
}

// ---------------- Final LN + logits + slice ----------------
__global__ void final_kernel(const float* __restrict__ gg, const float* __restrict__ bb,
                             const float* __restrict__ wl, float* __restrict__ out) {
    int row = blockIdx.x, c = threadIdx.x;
    int n = row & (N_ - 1);
    if (n < SLACK || n >= N_ - SLACK) return;
    float v = g_h[(size_t)row * LD + c];
    __shared__ float sh[16];
    __shared__ float stat[2];
    float s = v, sq = v * v;
    #pragma unroll
    for (int o = 16; o > 0; o >>= 1) {
        s  += __shfl_down_sync(0xffffffffu, s, o);
        sq += __shfl_down_sync(0xffffffffu, sq, o);
    }
    if ((c & 31) == 0) { sh[c >> 5] = s; sh[8 + (c >> 5)] = sq; }
    __syncthreads();
    if (c == 0) {
        float S = 0.f, SQ = 0.f;
        #pragma unroll
        for (int i = 0; i < 8; i++) { S += sh[i]; SQ += sh[8 + i]; }
        float mean = S * (1.f / LD);
        stat[0] = mean;
        stat[1] = rsqrtf(SQ * (1.f / LD) - mean * mean + 1e-5f);
    }
    __syncthreads();
    float contrib = ((v - stat[0]) * stat[1] * gg[c] + bb[c]) * wl[c];
    #pragma unroll
    for (int o = 16; o > 0; o >>= 1)
        contrib += __shfl_down_sync(0xffffffffu, contrib, o);
    __syncthreads();
    if ((c & 31) == 0) sh[c >> 5] = contrib;
    __syncthreads();
    if (c == 0) {
        float T = 0.f;
        #pragma unroll
        for (int i = 0; i < 8; i++) T += sh[i];
        int bidx = row >> 12;
        out[bidx * (N_ - 2 * SLACK) + (n - SLACK)] = T;
    }
}

// ---------------- Launch ----------------
extern "C" void kernel_launch(void* const* d_in, const int* in_sizes, int n_in,
                              void* d_out, int out_size) {
    const float* x        = (const float*)d_in[0];
    const float* W_exp    = (const float*)d_in[1];
    const float* b_exp    = (const float*)d_in[2];
    const float* pos_emb  = (const float*)d_in[3];
    const float* ln_att_g = (const float*)d_in[4];
    const float* ln_att_b = (const float*)d_in[5];
    const float* Wqkv     = (const float*)d_in[6];
    const float* Wout     = (const float*)d_in[7];
    const float* ln_ff_g  = (const float*)d_in[8];
    const float* ln_ff_b  = (const float*)d_in[9];
    const float* W1       = (const float*)d_in[10];
    const float* b1       = (const float*)d_in[11];
    const float* W2       = (const float*)d_in[12];
    const float* b2       = (const float*)d_in[13];
    const float* ln_f_g   = (const float*)d_in[14];
    const float* ln_f_b   = (const float*)d_in[15];
    const float* W_logits = (const float*)d_in[16];
    float* out = (float*)d_out;

    float *ph;
    __half *pyh, *pqkvh, *poh, *pffh;
    unsigned *pwp;
    cudaGetSymbolAddress((void**)&ph,    g_h);
    cudaGetSymbolAddress((void**)&pyh,   g_yh);
    cudaGetSymbolAddress((void**)&pqkvh, g_qkvh);
    cudaGetSymbolAddress((void**)&poh,   g_oh);
    cudaGetSymbolAddress((void**)&pffh,  g_ffh);
    cudaGetSymbolAddress((void**)&pwp,   g_wp);

    cudaFuncSetAttribute(attn_mma_kernel, cudaFuncAttributeMaxDynamicSharedMemorySize, ATTN_SMEM);
    cudaFuncSetAttribute(hgemm<0>, cudaFuncAttributeMaxDynamicSharedMemorySize, HG_SMEM);
    cudaFuncSetAttribute(hgemm<1>, cudaFuncAttributeMaxDynamicSharedMemorySize, HG_SMEM);
    cudaFuncSetAttribute((const void*)hgemm_ln<false, true>, cudaFuncAttributeMaxDynamicSharedMemorySize, FL_SMEM);
    cudaFuncSetAttribute((const void*)hgemm_ln<true,  true>, cudaFuncAttributeMaxDynamicSharedMemorySize, FL_SMEM);
    cudaFuncSetAttribute((const void*)hgemm_ln<true, false>, cudaFuncAttributeMaxDynamicSharedMemorySize, FL_SMEM);

    rope_table_kernel<<<(N_ * 32 + 255) / 256, 256>>>();
    pack_w_kernel<<<(786432 + 255) / 256, 256>>>(Wqkv, pwp + WQKV_OFF, DEPTH * LD / 2, QKVW);
    pack_w_kernel<<<(262144 + 255) / 256, 256>>>(Wout, pwp + WOUT_OFF, DEPTH * INNER / 2, LD);
    pack_w_kernel<<<(524288 + 255) / 256, 256>>>(W1,   pwp + W1_OFF,   DEPTH * LD / 2, FF);
    pack_w_kernel<<<(524288 + 255) / 256, 256>>>(W2,   pwp + W2_OFF,   DEPTH * FF / 2, LD);
    expand_kernel<<<R_, LD>>>(x, W_exp, b_exp, pos_emb);
    ln_kernel<<<R_, LD>>>(ph, pyh, ln_att_g, ln_att_b);   // layer-0 ln_attn

    for (int l = 0; l < DEPTH; ++l) {
        hgemm<0><<<dim3(QKVW / 128, R_ / 128), 256, HG_SMEM>>>(
            pyh, pwp + WQKV_OFF + (size_t)l * (LD / 2) * QKVW, pqkvh, nullptr, QKVW, LD);
        attn_mma_kernel<<<dim3(N_ / WW, H_, B_), 256, ATTN_SMEM>>>(pqkvh, poh);
        // Wout + residual + ln_ff  -> g_h, g_yh
        hgemm_ln<false, true><<<R_ / 64, 256, FL_SMEM>>>(
            poh, pwp + WOUT_OFF + (size_t)l * (INNER / 2) * LD, ph, nullptr,
            ln_ff_g + l * LD, ln_ff_b + l * LD, pyh, INNER);
        hgemm<1><<<dim3(FF / 128, R_ / 128), 256, HG_SMEM>>>(
            pyh, pwp + W1_OFF + (size_t)l * (LD / 2) * FF, pffh, b1 + (size_t)l * FF, FF, LD);
        // W2 + bias + residual (+ next layer's ln_attn) -> g_h (, g_yh)
        if (l < DEPTH - 1) {
            hgemm_ln<true, true><<<R_ / 64, 256, FL_SMEM>>>(
                pffh, pwp + W2_OFF + (size_t)l * (FF / 2) * LD, ph, b2 + (size_t)l * LD,
                ln_att_g + (l + 1) * LD, ln_att_b + (l + 1) * LD, pyh, FF);
        } else {
            hgemm_ln<true, false><<<R_ / 64, 256, FL_SMEM>>>(
                pffh, pwp + W2_OFF + (size_t)l * (FF / 2) * LD, ph, b2 + (size_t)l * LD,
                nullptr, nullptr, nullptr, FF);
        }
    }

    final_kernel<<<R_, LD>>>(ln_f_g, ln_f_b, W_logits, out);
}